// round 5
// baseline (speedup 1.0000x reference)
#include <cuda_runtime.h>
#include <cstdint>

// ToroidalSOM squared-distance: out[b, n] = ||x_b||^2 + ||w_n||^2 - 2 * dot(x_b, w_n)
// x: (128, 64) fp32, weights: (128*128, 64) fp32, out: (128, 16384) fp32.

#define DIM      64
#define BATCH    128
#define NTOT     16384
#define TILE_N   32
#define THREADS  256
#define XS       132   // x_s row stride in floats (pad: bank shift 4, 16B-aligned rows)
#define WS       36    // w_s row stride in floats (pad: bank shift 4, 16B/8B-aligned)

__global__ __launch_bounds__(THREADS)
void som_dist_kernel(const float* __restrict__ x,
                     const float* __restrict__ w,
                     float* __restrict__ out)
{
    __shared__ float x_s[DIM * XS];      // transposed: x_s[d][b]
    __shared__ float w_s[DIM * WS];      // transposed: w_s[d][n_local]
    __shared__ float xn_s[BATCH];        // ||x_b||^2
    __shared__ float wn_s[TILE_N];       // ||w_n||^2

    const int tid   = threadIdx.x;
    const int nbase = blockIdx.x * TILE_N;

    // ---- stage x transposed (8192 floats, coalesced global reads) ----
    #pragma unroll
    for (int i = 0; i < (BATCH * DIM) / THREADS; i++) {
        int idx = tid + i * THREADS;
        int b = idx >> 6, d = idx & 63;
        x_s[d * XS + b] = x[idx];
    }
    // ---- stage w tile transposed (2048 floats, coalesced) ----
    #pragma unroll
    for (int i = 0; i < (TILE_N * DIM) / THREADS; i++) {
        int idx = tid + i * THREADS;
        int n = idx >> 6, d = idx & 63;
        w_s[d * WS + n] = w[(size_t)nbase * DIM + idx];
    }
    __syncthreads();

    // ---- norms prologue ----
    if (tid < BATCH) {
        float s = 0.f;
        #pragma unroll 8
        for (int d = 0; d < DIM; d++) {
            float v = x_s[d * XS + tid];
            s = fmaf(v, v, s);
        }
        xn_s[tid] = s;
    } else if (tid < BATCH + TILE_N) {
        int n = tid - BATCH;
        float s = 0.f;
        #pragma unroll 8
        for (int d = 0; d < DIM; d++) {
            float v = w_s[d * WS + n];
            s = fmaf(v, v, s);
        }
        wn_s[n] = s;
    }
    __syncthreads();

    // ---- main loop: each thread does 8 batches x 2 neurons via f32x2 packed FMA ----
    const int nl = (tid & 15) * 2;   // 2 consecutive neurons
    const int b0 = (tid >> 4) * 8;   // 8 consecutive batches (4 f32x2 pairs)

    unsigned long long acc[4][2];
    #pragma unroll
    for (int i = 0; i < 4; i++) { acc[i][0] = 0ULL; acc[i][1] = 0ULL; }

    #pragma unroll 8
    for (int k = 0; k < DIM; k++) {
        // 4 packed x pairs: batches (b0..b0+7), 16B-aligned -> LDS.128 x2
        const unsigned long long* xr =
            (const unsigned long long*)&x_s[k * XS + b0];
        unsigned long long xp0 = xr[0];
        unsigned long long xp1 = xr[1];
        unsigned long long xp2 = xr[2];
        unsigned long long xp3 = xr[3];

        // 2 neuron weights, broadcast-duplicated into f32x2
        float2 wv = *(const float2*)&w_s[k * WS + nl];
        unsigned long long wp0, wp1;
        asm("mov.b64 %0, {%1, %1};" : "=l"(wp0) : "f"(wv.x));
        asm("mov.b64 %0, {%1, %1};" : "=l"(wp1) : "f"(wv.y));

        asm("fma.rn.f32x2 %0, %1, %2, %0;" : "+l"(acc[0][0]) : "l"(xp0), "l"(wp0));
        asm("fma.rn.f32x2 %0, %1, %2, %0;" : "+l"(acc[0][1]) : "l"(xp0), "l"(wp1));
        asm("fma.rn.f32x2 %0, %1, %2, %0;" : "+l"(acc[1][0]) : "l"(xp1), "l"(wp0));
        asm("fma.rn.f32x2 %0, %1, %2, %0;" : "+l"(acc[1][1]) : "l"(xp1), "l"(wp1));
        asm("fma.rn.f32x2 %0, %1, %2, %0;" : "+l"(acc[2][0]) : "l"(xp2), "l"(wp0));
        asm("fma.rn.f32x2 %0, %1, %2, %0;" : "+l"(acc[2][1]) : "l"(xp2), "l"(wp1));
        asm("fma.rn.f32x2 %0, %1, %2, %0;" : "+l"(acc[3][0]) : "l"(xp3), "l"(wp0));
        asm("fma.rn.f32x2 %0, %1, %2, %0;" : "+l"(acc[3][1]) : "l"(xp3), "l"(wp1));
    }

    // ---- epilogue: dist = xn + wn - 2*dot; coalesced float2 stores ----
    const float wn0 = wn_s[nl];
    const float wn1 = wn_s[nl + 1];

    #pragma unroll
    for (int i = 0; i < 4; i++) {
        float a0lo, a0hi, a1lo, a1hi;
        asm("mov.b64 {%0, %1}, %2;" : "=f"(a0lo), "=f"(a0hi) : "l"(acc[i][0]));
        asm("mov.b64 {%0, %1}, %2;" : "=f"(a1lo), "=f"(a1hi) : "l"(acc[i][1]));

        int b = b0 + 2 * i;
        float xnv0 = xn_s[b];
        float xnv1 = xn_s[b + 1];

        float2 r0, r1;
        r0.x = fmaf(-2.f, a0lo, xnv0 + wn0);
        r0.y = fmaf(-2.f, a1lo, xnv0 + wn1);
        r1.x = fmaf(-2.f, a0hi, xnv1 + wn0);
        r1.y = fmaf(-2.f, a1hi, xnv1 + wn1);

        *(float2*)&out[(size_t)b       * NTOT + nbase + nl] = r0;
        *(float2*)&out[(size_t)(b + 1) * NTOT + nbase + nl] = r1;
    }
}

extern "C" void kernel_launch(void* const* d_in, const int* in_sizes, int n_in,
                              void* d_out, int out_size)
{
    const float* x = (const float*)d_in[0];   // (128, 64)
    const float* w = (const float*)d_in[1];   // (16384, 64)
    float* out = (float*)d_out;               // (128, 16384)

    som_dist_kernel<<<NTOT / TILE_N, THREADS>>>(x, w, out);
}